// round 5
// baseline (speedup 1.0000x reference)
#include <cuda_runtime.h>
#include <math.h>

// Problem constants (fixed by the dataset)
#define NN   50000
#define EE   1600000       // edges (self loops handled analytically)
#define C1   128           // H * HID (layer 1 output channels)
#define C2   64            // layer 2 output channels

// ---------------- scratch (static device globals; no allocation) ------------
__device__ float g_xh1 [NN * C1];   // x @ W1
__device__ float g_h1  [NN * C1];   // layer-1 output (after norm+bias+relu)
__device__ float g_xh2 [NN * C2];   // h1 @ W2
__device__ float g_ssrc1[NN * 2];
__device__ float g_sdst1[NN * 2];
__device__ float g_ssrc2[NN];
__device__ float g_sdst2[NN];
__device__ int   g_deg   [NN];
__device__ int   g_rowptr[NN + 1];
__device__ int   g_cursor[NN];
__device__ int   g_csrc  [EE];

__device__ __forceinline__ float leaky(float x) { return x > 0.f ? x : 0.2f * x; }

// packed f32x2 helpers (FFMA2 is only reachable via PTX fma.rn.f32x2)
__device__ __forceinline__ unsigned long long pack2(float lo, float hi) {
    unsigned long long r;
    asm("mov.b64 %0, {%1, %2};" : "=l"(r) : "f"(lo), "f"(hi));
    return r;
}
__device__ __forceinline__ unsigned long long fma2(unsigned long long a,
                                                   unsigned long long b,
                                                   unsigned long long c) {
    unsigned long long d;
    asm("fma.rn.f32x2 %0, %1, %2, %3;" : "=l"(d) : "l"(a), "l"(b), "l"(c));
    return d;
}
__device__ __forceinline__ float sum2(unsigned long long v) {
    float a, b;
    asm("mov.b64 {%0, %1}, %2;" : "=f"(a), "=f"(b) : "l"(v));
    return a + b;
}

// ---------------- CSR build (edges only; no self-loops) ---------------------
// 8 edges per thread for atomic MLP
__global__ void hist_kernel(const int* __restrict__ ei) {
    int t = blockIdx.x * blockDim.x + threadIdx.x;
    if (t >= EE / 8) return;
    int4 a = ((const int4*)(ei + EE))[t * 2];
    int4 b = ((const int4*)(ei + EE))[t * 2 + 1];
    atomicAdd(&g_deg[a.x], 1);
    atomicAdd(&g_deg[a.y], 1);
    atomicAdd(&g_deg[a.z], 1);
    atomicAdd(&g_deg[a.w], 1);
    atomicAdd(&g_deg[b.x], 1);
    atomicAdd(&g_deg[b.y], 1);
    atomicAdd(&g_deg[b.z], 1);
    atomicAdd(&g_deg[b.w], 1);
}

// single-block exclusive scan, 4 elements / thread / chunk (1024 threads)
__global__ void scan_kernel() {
    __shared__ int wsum[32];
    __shared__ int carry_s;
    const int tid = threadIdx.x, lane = tid & 31, wid = tid >> 5;
    if (tid == 0) carry_s = 0;
    __syncthreads();
    for (int base = 0; base < NN; base += 4096) {
        int i0 = base + tid * 4;
        int v0 = 0, v1 = 0, v2 = 0, v3 = 0;
        if (i0 + 3 < NN) {
            int4 v = *(const int4*)&g_deg[i0];
            v0 = v.x; v1 = v.y; v2 = v.z; v3 = v.w;
        } else if (i0 < NN) {
            v0 = g_deg[i0];
            if (i0 + 1 < NN) v1 = g_deg[i0 + 1];
            if (i0 + 2 < NN) v2 = g_deg[i0 + 2];
        }
        int t = v0 + v1 + v2 + v3;
        int x = t;
#pragma unroll
        for (int off = 1; off < 32; off <<= 1) {
            int y = __shfl_up_sync(0xffffffffu, x, off);
            if (lane >= off) x += y;
        }
        if (lane == 31) wsum[wid] = x;
        __syncthreads();
        if (wid == 0) {
            int s = wsum[lane];
#pragma unroll
            for (int off = 1; off < 32; off <<= 1) {
                int y = __shfl_up_sync(0xffffffffu, s, off);
                if (lane >= off) s += y;
            }
            wsum[lane] = s;
        }
        __syncthreads();
        int carry = carry_s;
        int pref = carry + (wid ? wsum[wid - 1] : 0) + (x - t);
        if (i0 < NN)     { g_rowptr[i0]     = pref;                g_cursor[i0]     = pref; }
        if (i0 + 1 < NN) { g_rowptr[i0 + 1] = pref + v0;           g_cursor[i0 + 1] = pref + v0; }
        if (i0 + 2 < NN) { g_rowptr[i0 + 2] = pref + v0 + v1;      g_cursor[i0 + 2] = pref + v0 + v1; }
        if (i0 + 3 < NN) { g_rowptr[i0 + 3] = pref + v0 + v1 + v2; g_cursor[i0 + 3] = pref + v0 + v1 + v2; }
        __syncthreads();
        if (tid == 0) carry_s = carry + wsum[31];
        __syncthreads();
    }
    if (threadIdx.x == 0) g_rowptr[NN] = carry_s;   // == EE
}

__global__ void scatter_kernel(const int* __restrict__ ei) {
    int t = blockIdx.x * blockDim.x + threadIdx.x;
    if (t >= EE / 8) return;
    int4 sa = ((const int4*)ei)[t * 2];
    int4 sb = ((const int4*)ei)[t * 2 + 1];
    int4 da = ((const int4*)(ei + EE))[t * 2];
    int4 db = ((const int4*)(ei + EE))[t * 2 + 1];
    int p0 = atomicAdd(&g_cursor[da.x], 1);
    int p1 = atomicAdd(&g_cursor[da.y], 1);
    int p2 = atomicAdd(&g_cursor[da.z], 1);
    int p3 = atomicAdd(&g_cursor[da.w], 1);
    int p4 = atomicAdd(&g_cursor[db.x], 1);
    int p5 = atomicAdd(&g_cursor[db.y], 1);
    int p6 = atomicAdd(&g_cursor[db.z], 1);
    int p7 = atomicAdd(&g_cursor[db.w], 1);
    g_csrc[p0] = sa.x;
    g_csrc[p1] = sa.y;
    g_csrc[p2] = sa.z;
    g_csrc[p3] = sa.w;
    g_csrc[p4] = sb.x;
    g_csrc[p5] = sb.y;
    g_csrc[p6] = sb.z;
    g_csrc[p7] = sb.w;
}

// ---------------- GEMM v3: k-parity packed FFMA2 ----------------------------
// Accumulators hold (sum over even k, sum over odd k) per (row,col);
// A operand (A[k],A[k+1]) comes straight from smem as one LDS.64 — no packing.
// B packs once per 2-k per column. Halves of acc summed in epilogue.
template <int LAYER>
__global__ void gemm_kernel(const float* __restrict__ Aext,
                            const float* __restrict__ B,
                            const float* __restrict__ asrc,
                            const float* __restrict__ adst) {
    constexpr int NOUT = (LAYER == 1) ? C1 : C2;
    constexpr int CPT  = NOUT / 32;                // cols per thread (4 or 2)
    const float* A  = (LAYER == 1) ? Aext : g_h1;
    float*       Cp = (LAYER == 1) ? g_xh1 : g_xh2;
    float*       Ss = (LAYER == 1) ? g_ssrc1 : g_ssrc2;
    float*       Sd = (LAYER == 1) ? g_sdst1 : g_sdst2;

    __shared__ float As[64 * 128];

    const int tid = threadIdx.x;   // 256 threads
    const int block_row = blockIdx.x * 64;

    for (int i = tid; i < 64 * 32; i += 256) {
        int r = i >> 5, c4 = i & 31;
        int gr = block_row + r;
        float4 v = (gr < NN) ? ((const float4*)(A + (size_t)gr * 128))[c4]
                             : make_float4(0.f, 0.f, 0.f, 0.f);
        ((float4*)As)[i] = v;
    }
    __syncthreads();

    const int tx = tid & 31;
    const int ty = tid >> 5;
    const int row0 = ty * 8;
    const float* Bcol = B + tx * CPT;              // this thread's columns

    unsigned long long acc[8][CPT];
#pragma unroll
    for (int r = 0; r < 8; ++r)
#pragma unroll
        for (int c = 0; c < CPT; ++c) acc[r][c] = 0ull;

#pragma unroll 4
    for (int k = 0; k < 128; k += 2) {
        // B rows k and k+1, this thread's CPT columns
        float bk[CPT], bk1[CPT];
        if constexpr (CPT == 4) {
            float4 t0 = __ldg((const float4*)(Bcol + (size_t)k * NOUT));
            float4 t1 = __ldg((const float4*)(Bcol + (size_t)(k + 1) * NOUT));
            bk[0] = t0.x; bk[1] = t0.y; bk[2] = t0.z; bk[3] = t0.w;
            bk1[0] = t1.x; bk1[1] = t1.y; bk1[2] = t1.z; bk1[3] = t1.w;
        } else {
            float2 t0 = __ldg((const float2*)(Bcol + (size_t)k * NOUT));
            float2 t1 = __ldg((const float2*)(Bcol + (size_t)(k + 1) * NOUT));
            bk[0] = t0.x; bk[1] = t0.y;
            bk1[0] = t1.x; bk1[1] = t1.y;
        }
        unsigned long long pb[CPT];
#pragma unroll
        for (int c = 0; c < CPT; ++c) pb[c] = pack2(bk[c], bk1[c]);

#pragma unroll
        for (int r = 0; r < 8; ++r) {
            // (A[k], A[k+1]) contiguous: one broadcast LDS.64
            unsigned long long a =
                *(const unsigned long long*)&As[(row0 + r) * 128 + k];
#pragma unroll
            for (int c = 0; c < CPT; ++c)
                acc[r][c] = fma2(a, pb[c], acc[r][c]);
        }
    }

    float av[CPT], dv[CPT];
#pragma unroll
    for (int c = 0; c < CPT; ++c) {
        av[c] = asrc[tx * CPT + c];
        dv[c] = adst[tx * CPT + c];
    }

#pragma unroll
    for (int r = 0; r < 8; ++r) {
        int gr = block_row + row0 + r;
        float o[CPT];
#pragma unroll
        for (int c = 0; c < CPT; ++c) o[c] = sum2(acc[r][c]);

        float ps = 0.f, pd = 0.f;
#pragma unroll
        for (int c = 0; c < CPT; ++c) {
            ps = fmaf(o[c], av[c], ps);
            pd = fmaf(o[c], dv[c], pd);
        }
        if constexpr (LAYER == 1) {
#pragma unroll
            for (int off = 8; off > 0; off >>= 1) {
                ps += __shfl_xor_sync(0xffffffffu, ps, off, 16);
                pd += __shfl_xor_sync(0xffffffffu, pd, off, 16);
            }
            if (gr < NN && (tx & 15) == 0) {
                int h = tx >> 4;
                Ss[gr * 2 + h] = ps;
                Sd[gr * 2 + h] = pd;
            }
        } else {
#pragma unroll
            for (int off = 16; off > 0; off >>= 1) {
                ps += __shfl_xor_sync(0xffffffffu, ps, off);
                pd += __shfl_xor_sync(0xffffffffu, pd, off);
            }
            if (gr < NN && tx == 0) { Ss[gr] = ps; Sd[gr] = pd; }
        }
        if (gr < NN) {
            if constexpr (CPT == 4) {
                float4 st = make_float4(o[0], o[1], o[2], o[3]);
                *(float4*)(Cp + (size_t)gr * NOUT + tx * 4) = st;
            } else {
                float2 st = make_float2(o[0], o[1]);
                *(float2*)(Cp + (size_t)gr * NOUT + tx * 2) = st;
            }
        }
    }
}

// ---------------- layer-1 aggregation: warp per dst node --------------------
// softmax without max-subtraction (shift-invariant); self-loop added analytically
__global__ void agg1_kernel(const float* __restrict__ b1) {
    int gt = blockIdx.x * blockDim.x + threadIdx.x;
    int w = gt >> 5;
    if (w >= NN) return;
    int lane = gt & 31;
    int h = lane >> 4;
    float sd = g_sdst1[w * 2 + h];

    // self loop (src == dst == w)
    float p = __expf(leaky(g_ssrc1[w * 2 + h] + sd));
    float den = p;
    float4 v = *(const float4*)&g_xh1[(size_t)w * C1 + lane * 4];
    float a0 = v.x * p, a1 = v.y * p, a2 = v.z * p, a3 = v.w * p;

    int beg = g_rowptr[w], end = g_rowptr[w + 1];
#pragma unroll 4
    for (int e = beg; e < end; ++e) {
        int s = __ldg(&g_csrc[e]);
        float pp = __expf(leaky(g_ssrc1[s * 2 + h] + sd));
        den += pp;
        float4 u = *(const float4*)&g_xh1[(size_t)s * C1 + lane * 4];
        a0 = fmaf(u.x, pp, a0);
        a1 = fmaf(u.y, pp, a1);
        a2 = fmaf(u.z, pp, a2);
        a3 = fmaf(u.w, pp, a3);
    }
    float inv = 1.f / (den + 1e-16f);
    int c = lane * 4;
    float4 o;
    o.x = fmaf(a0, inv, b1[c]);
    o.y = fmaf(a1, inv, b1[c + 1]);
    o.z = fmaf(a2, inv, b1[c + 2]);
    o.w = fmaf(a3, inv, b1[c + 3]);
    o.x = o.x > 0.f ? o.x : 0.f;
    o.y = o.y > 0.f ? o.y : 0.f;
    o.z = o.z > 0.f ? o.z : 0.f;
    o.w = o.w > 0.f ? o.w : 0.f;
    *(float4*)&g_h1[(size_t)w * C1 + c] = o;
}

// ---------------- layer-2 aggregation + epilogue + output heads -------------
__global__ void agg2_kernel(const float* __restrict__ b2,
                            const float* __restrict__ Wm,
                            const float* __restrict__ bm,
                            const float* __restrict__ Wl,
                            const float* __restrict__ bl,
                            float* __restrict__ out) {
    int gt = blockIdx.x * blockDim.x + threadIdx.x;
    int w = gt >> 5;
    if (w >= NN) return;
    int lane = gt & 31;
    float sd = g_sdst2[w];

    // self loop
    float p = __expf(leaky(g_ssrc2[w] + sd));
    float den = p;
    float2 v = *(const float2*)&g_xh2[(size_t)w * C2 + lane * 2];
    float a0 = v.x * p, a1 = v.y * p;

    int beg = g_rowptr[w], end = g_rowptr[w + 1];
#pragma unroll 4
    for (int e = beg; e < end; ++e) {
        int s = __ldg(&g_csrc[e]);
        float pp = __expf(leaky(g_ssrc2[s] + sd));
        den += pp;
        float2 u = *(const float2*)&g_xh2[(size_t)s * C2 + lane * 2];
        a0 = fmaf(u.x, pp, a0);
        a1 = fmaf(u.y, pp, a1);
    }
    float inv = 1.f / (den + 1e-16f);
    int j0 = lane * 2;
    float v0 = fmaf(a0, inv, b2[j0]);
    float v1 = fmaf(a1, inv, b2[j0 + 1]);
    v0 = v0 > 0.f ? v0 : 0.f;
    v1 = v1 > 0.f ? v1 : 0.f;
    float m = v0 * Wm[j0] + v1 * Wm[j0 + 1];
    float l0 = v0 * Wl[j0 * 4 + 0] + v1 * Wl[(j0 + 1) * 4 + 0];
    float l1 = v0 * Wl[j0 * 4 + 1] + v1 * Wl[(j0 + 1) * 4 + 1];
    float l2 = v0 * Wl[j0 * 4 + 2] + v1 * Wl[(j0 + 1) * 4 + 2];
    float l3 = v0 * Wl[j0 * 4 + 3] + v1 * Wl[(j0 + 1) * 4 + 3];
#pragma unroll
    for (int off = 16; off > 0; off >>= 1) {
        m  += __shfl_xor_sync(0xffffffffu, m,  off);
        l0 += __shfl_xor_sync(0xffffffffu, l0, off);
        l1 += __shfl_xor_sync(0xffffffffu, l1, off);
        l2 += __shfl_xor_sync(0xffffffffu, l2, off);
        l3 += __shfl_xor_sync(0xffffffffu, l3, off);
    }
    if (lane == 0) {
        out[w] = m + bm[0];                     // mortality [N,1]
        float4 lo = make_float4(l0 + bl[0], l1 + bl[1], l2 + bl[2], l3 + bl[3]);
        *(float4*)&out[NN + (size_t)w * 4] = lo;   // los [N,4]
    }
}

// ---------------- launch ----------------------------------------------------
extern "C" void kernel_launch(void* const* d_in, const int* in_sizes, int n_in,
                              void* d_out, int out_size) {
    const float* x      = (const float*)d_in[0];
    const int*   ei     = (const int*)  d_in[1];
    const float* W1     = (const float*)d_in[2];
    const float* a_src1 = (const float*)d_in[3];
    const float* a_dst1 = (const float*)d_in[4];
    const float* b1     = (const float*)d_in[5];
    const float* W2     = (const float*)d_in[6];
    const float* a_src2 = (const float*)d_in[7];
    const float* a_dst2 = (const float*)d_in[8];
    const float* b2     = (const float*)d_in[9];
    const float* Wm     = (const float*)d_in[10];
    const float* bm     = (const float*)d_in[11];
    const float* Wl     = (const float*)d_in[12];
    const float* bl     = (const float*)d_in[13];
    float* out = (float*)d_out;

    const int gemm_blocks = (NN + 63) / 64;

    void* degAddr = nullptr;
    cudaGetSymbolAddress(&degAddr, g_deg);

    // fork a side stream for the CSR build (overlaps with gemm1).
    // created fresh each call and intentionally leaked (host objects only).
    cudaStream_t side;
    cudaStreamCreateWithFlags(&side, cudaStreamNonBlocking);
    cudaEvent_t evFork, evJoin;
    cudaEventCreateWithFlags(&evFork, cudaEventDisableTiming);
    cudaEventCreateWithFlags(&evJoin, cudaEventDisableTiming);

    cudaEventRecord(evFork, 0);
    cudaStreamWaitEvent(side, evFork, 0);

    // ---- CSR build on side stream ----
    cudaMemsetAsync(degAddr, 0, NN * sizeof(int), side);
    hist_kernel<<<(EE / 8 + 255) / 256, 256, 0, side>>>(ei);
    scan_kernel<<<1, 1024, 0, side>>>();
    scatter_kernel<<<(EE / 8 + 255) / 256, 256, 0, side>>>(ei);
    cudaEventRecord(evJoin, side);

    // ---- gemm1 on main stream (independent of CSR) ----
    gemm_kernel<1><<<gemm_blocks, 256>>>(x, W1, a_src1, a_dst1);

    // join: agg1 needs both CSR and gemm1
    cudaStreamWaitEvent(0, evJoin, 0);

    agg1_kernel<<<(NN * 32 + 255) / 256, 256>>>(b1);
    gemm_kernel<2><<<gemm_blocks, 256>>>(nullptr, W2, a_src2, a_dst2);
    agg2_kernel<<<(NN * 32 + 255) / 256, 256>>>(b2, Wm, bm, Wl, bl, out);
}

// round 6
// speedup vs baseline: 1.1776x; 1.1776x over previous
#include <cuda_runtime.h>
#include <cuda_fp16.h>
#include <math.h>

// Problem constants (fixed by the dataset)
#define NN   50000
#define EE   1600000       // edges (self loops handled analytically)
#define C1   128           // H * HID (layer 1 output channels)
#define C2   64            // layer 2 output channels

// ---------------- scratch (static device globals; no allocation) ------------
__device__ __half g_xh1h[NN * C1];  // x @ W1   (fp16 gather payload)
__device__ __half g_xh2h[NN * C2];  // h1 @ W2  (fp16 gather payload)
__device__ float  g_h1  [NN * C1];  // layer-1 output (after norm+bias+relu)
__device__ float  g_ssrc1[NN * 2];
__device__ float  g_sdst1[NN * 2];
__device__ float  g_ssrc2[NN];
__device__ float  g_sdst2[NN];
__device__ int    g_deg   [NN];
__device__ int    g_rowptr[NN + 1];
__device__ int    g_cursor[NN];
__device__ int    g_csrc  [EE];

__device__ __forceinline__ float leaky(float x) { return x > 0.f ? x : 0.2f * x; }

// packed f32x2 helpers (FFMA2 only reachable via PTX fma.rn.f32x2)
__device__ __forceinline__ unsigned long long pack2(float lo, float hi) {
    unsigned long long r;
    asm("mov.b64 %0, {%1, %2};" : "=l"(r) : "f"(lo), "f"(hi));
    return r;
}
__device__ __forceinline__ unsigned long long fma2(unsigned long long a,
                                                   unsigned long long b,
                                                   unsigned long long c) {
    unsigned long long d;
    asm("fma.rn.f32x2 %0, %1, %2, %3;" : "=l"(d) : "l"(a), "l"(b), "l"(c));
    return d;
}
__device__ __forceinline__ float lo2(unsigned long long v) {
    float a, b;
    asm("mov.b64 {%0, %1}, %2;" : "=f"(a), "=f"(b) : "l"(v));
    return a;
}
__device__ __forceinline__ float hi2(unsigned long long v) {
    float a, b;
    asm("mov.b64 {%0, %1}, %2;" : "=f"(a), "=f"(b) : "l"(v));
    return b;
}

// ---------------- CSR build (edges only; no self-loops) ---------------------
__global__ void hist_kernel(const int* __restrict__ ei) {
    int t = blockIdx.x * blockDim.x + threadIdx.x;
    if (t >= EE / 8) return;
    int4 a = ((const int4*)(ei + EE))[t * 2];
    int4 b = ((const int4*)(ei + EE))[t * 2 + 1];
    atomicAdd(&g_deg[a.x], 1);
    atomicAdd(&g_deg[a.y], 1);
    atomicAdd(&g_deg[a.z], 1);
    atomicAdd(&g_deg[a.w], 1);
    atomicAdd(&g_deg[b.x], 1);
    atomicAdd(&g_deg[b.y], 1);
    atomicAdd(&g_deg[b.z], 1);
    atomicAdd(&g_deg[b.w], 1);
}

// single-block exclusive scan, 4 elements / thread / chunk (1024 threads)
__global__ void scan_kernel() {
    __shared__ int wsum[32];
    __shared__ int carry_s;
    const int tid = threadIdx.x, lane = tid & 31, wid = tid >> 5;
    if (tid == 0) carry_s = 0;
    __syncthreads();
    for (int base = 0; base < NN; base += 4096) {
        int i0 = base + tid * 4;
        int v0 = 0, v1 = 0, v2 = 0, v3 = 0;
        if (i0 + 3 < NN) {
            int4 v = *(const int4*)&g_deg[i0];
            v0 = v.x; v1 = v.y; v2 = v.z; v3 = v.w;
        } else if (i0 < NN) {
            v0 = g_deg[i0];
            if (i0 + 1 < NN) v1 = g_deg[i0 + 1];
            if (i0 + 2 < NN) v2 = g_deg[i0 + 2];
        }
        int t = v0 + v1 + v2 + v3;
        int x = t;
#pragma unroll
        for (int off = 1; off < 32; off <<= 1) {
            int y = __shfl_up_sync(0xffffffffu, x, off);
            if (lane >= off) x += y;
        }
        if (lane == 31) wsum[wid] = x;
        __syncthreads();
        if (wid == 0) {
            int s = wsum[lane];
#pragma unroll
            for (int off = 1; off < 32; off <<= 1) {
                int y = __shfl_up_sync(0xffffffffu, s, off);
                if (lane >= off) s += y;
            }
            wsum[lane] = s;
        }
        __syncthreads();
        int carry = carry_s;
        int pref = carry + (wid ? wsum[wid - 1] : 0) + (x - t);
        if (i0 < NN)     { g_rowptr[i0]     = pref;                g_cursor[i0]     = pref; }
        if (i0 + 1 < NN) { g_rowptr[i0 + 1] = pref + v0;           g_cursor[i0 + 1] = pref + v0; }
        if (i0 + 2 < NN) { g_rowptr[i0 + 2] = pref + v0 + v1;      g_cursor[i0 + 2] = pref + v0 + v1; }
        if (i0 + 3 < NN) { g_rowptr[i0 + 3] = pref + v0 + v1 + v2; g_cursor[i0 + 3] = pref + v0 + v1 + v2; }
        __syncthreads();
        if (tid == 0) carry_s = carry + wsum[31];
        __syncthreads();
    }
    if (threadIdx.x == 0) g_rowptr[NN] = carry_s;   // == EE
}

__global__ void scatter_kernel(const int* __restrict__ ei) {
    int t = blockIdx.x * blockDim.x + threadIdx.x;
    if (t >= EE / 8) return;
    int4 sa = ((const int4*)ei)[t * 2];
    int4 sb = ((const int4*)ei)[t * 2 + 1];
    int4 da = ((const int4*)(ei + EE))[t * 2];
    int4 db = ((const int4*)(ei + EE))[t * 2 + 1];
    int p0 = atomicAdd(&g_cursor[da.x], 1);
    int p1 = atomicAdd(&g_cursor[da.y], 1);
    int p2 = atomicAdd(&g_cursor[da.z], 1);
    int p3 = atomicAdd(&g_cursor[da.w], 1);
    int p4 = atomicAdd(&g_cursor[db.x], 1);
    int p5 = atomicAdd(&g_cursor[db.y], 1);
    int p6 = atomicAdd(&g_cursor[db.z], 1);
    int p7 = atomicAdd(&g_cursor[db.w], 1);
    g_csrc[p0] = sa.x;
    g_csrc[p1] = sa.y;
    g_csrc[p2] = sa.z;
    g_csrc[p3] = sa.w;
    g_csrc[p4] = sb.x;
    g_csrc[p5] = sb.y;
    g_csrc[p6] = sb.z;
    g_csrc[p7] = sb.w;
}

// ---------------- GEMM (Round-4 FFMA2 form) + fused scores, fp16 output -----
template <int LAYER>
__global__ void gemm_kernel(const float* __restrict__ Aext,
                            const float* __restrict__ B,
                            const float* __restrict__ asrc,
                            const float* __restrict__ adst) {
    constexpr int NOUT = (LAYER == 1) ? C1 : C2;
    constexpr int CPT  = NOUT / 32;                // cols per thread (4 or 2)
    constexpr int CP2  = CPT / 2;                  // packed pairs (2 or 1)
    const float* A  = (LAYER == 1) ? Aext : g_h1;
    __half*      Hp = (LAYER == 1) ? g_xh1h : g_xh2h;
    float*       Ss = (LAYER == 1) ? g_ssrc1 : g_ssrc2;
    float*       Sd = (LAYER == 1) ? g_sdst1 : g_sdst2;

    __shared__ float As[64 * 128];

    const int tid = threadIdx.x;   // 256 threads
    const int block_row = blockIdx.x * 64;

    for (int i = tid; i < 64 * 32; i += 256) {
        int r = i >> 5, c4 = i & 31;
        int gr = block_row + r;
        float4 v = (gr < NN) ? ((const float4*)(A + (size_t)gr * 128))[c4]
                             : make_float4(0.f, 0.f, 0.f, 0.f);
        ((float4*)As)[i] = v;
    }
    __syncthreads();

    const int tx = tid & 31;
    const int ty = tid >> 5;
    const int row0 = ty * 8;
    const float* Bcol = B + tx * CPT;              // this thread's columns

    unsigned long long acc[8][CP2];
#pragma unroll
    for (int r = 0; r < 8; ++r)
#pragma unroll
        for (int j = 0; j < CP2; ++j) acc[r][j] = 0ull;

#pragma unroll 2
    for (int k = 0; k < 128; k += 2) {
        unsigned long long b0[CP2], b1[CP2];
        if constexpr (CP2 == 2) {
            ulonglong2 t0 = __ldg((const ulonglong2*)(Bcol + (size_t)k * NOUT));
            ulonglong2 t1 = __ldg((const ulonglong2*)(Bcol + (size_t)(k + 1) * NOUT));
            b0[0] = t0.x; b0[1] = t0.y;
            b1[0] = t1.x; b1[1] = t1.y;
        } else {
            b0[0] = __ldg((const unsigned long long*)(Bcol + (size_t)k * NOUT));
            b1[0] = __ldg((const unsigned long long*)(Bcol + (size_t)(k + 1) * NOUT));
        }
#pragma unroll
        for (int r = 0; r < 8; ++r) {
            unsigned long long a0 = pack2(As[(row0 + r) * 128 + k],
                                          As[(row0 + r) * 128 + k]);
            unsigned long long a1 = pack2(As[(row0 + r) * 128 + k + 1],
                                          As[(row0 + r) * 128 + k + 1]);
#pragma unroll
            for (int j = 0; j < CP2; ++j) {
                acc[r][j] = fma2(a0, b0[j], acc[r][j]);
                acc[r][j] = fma2(a1, b1[j], acc[r][j]);
            }
        }
    }

    float av[CPT], dv[CPT];
#pragma unroll
    for (int c = 0; c < CPT; ++c) {
        av[c] = asrc[tx * CPT + c];
        dv[c] = adst[tx * CPT + c];
    }

#pragma unroll
    for (int r = 0; r < 8; ++r) {
        int gr = block_row + row0 + r;
        float o[CPT];
#pragma unroll
        for (int j = 0; j < CP2; ++j) {
            o[j * 2]     = lo2(acc[r][j]);
            o[j * 2 + 1] = hi2(acc[r][j]);
        }
        float ps = 0.f, pd = 0.f;
#pragma unroll
        for (int c = 0; c < CPT; ++c) {
            ps = fmaf(o[c], av[c], ps);
            pd = fmaf(o[c], dv[c], pd);
        }
        if constexpr (LAYER == 1) {
#pragma unroll
            for (int off = 8; off > 0; off >>= 1) {
                ps += __shfl_xor_sync(0xffffffffu, ps, off, 16);
                pd += __shfl_xor_sync(0xffffffffu, pd, off, 16);
            }
            if (gr < NN && (tx & 15) == 0) {
                int h = tx >> 4;
                Ss[gr * 2 + h] = ps;
                Sd[gr * 2 + h] = pd;
            }
        } else {
#pragma unroll
            for (int off = 16; off > 0; off >>= 1) {
                ps += __shfl_xor_sync(0xffffffffu, ps, off);
                pd += __shfl_xor_sync(0xffffffffu, pd, off);
            }
            if (gr < NN && tx == 0) { Ss[gr] = ps; Sd[gr] = pd; }
        }
        if (gr < NN) {
            __half2* dsth = (__half2*)(Hp + (size_t)gr * NOUT + tx * CPT);
#pragma unroll
            for (int j = 0; j < CP2; ++j)
                dsth[j] = __floats2half2_rn(o[j * 2], o[j * 2 + 1]);
        }
    }
}

// ---------------- layer-1 aggregation: warp per dst node, fp16 gather -------
// softmax without max-subtraction (shift-invariant); self-loop added analytically
__global__ void agg1_kernel(const float* __restrict__ b1) {
    int gt = blockIdx.x * blockDim.x + threadIdx.x;
    int w = gt >> 5;
    if (w >= NN) return;
    int lane = gt & 31;
    int h = lane >> 4;
    float sd = g_sdst1[w * 2 + h];

    // self loop (src == dst == w)
    float p = __expf(leaky(g_ssrc1[w * 2 + h] + sd));
    float den = p;
    uint2 raw = *(const uint2*)(g_xh1h + (size_t)w * C1 + lane * 4);
    float2 u0 = __half22float2(*(__half2*)&raw.x);
    float2 u1 = __half22float2(*(__half2*)&raw.y);
    float a0 = u0.x * p, a1 = u0.y * p, a2 = u1.x * p, a3 = u1.y * p;

    int beg = g_rowptr[w], end = g_rowptr[w + 1];
#pragma unroll 4
    for (int e = beg; e < end; ++e) {
        int s = __ldg(&g_csrc[e]);
        float pp = __expf(leaky(g_ssrc1[s * 2 + h] + sd));
        den += pp;
        uint2 rw = __ldg((const uint2*)(g_xh1h + (size_t)s * C1 + lane * 4));
        float2 v0 = __half22float2(*(__half2*)&rw.x);
        float2 v1 = __half22float2(*(__half2*)&rw.y);
        a0 = fmaf(v0.x, pp, a0);
        a1 = fmaf(v0.y, pp, a1);
        a2 = fmaf(v1.x, pp, a2);
        a3 = fmaf(v1.y, pp, a3);
    }
    float inv = 1.f / (den + 1e-16f);
    int c = lane * 4;
    float4 o;
    o.x = fmaf(a0, inv, b1[c]);
    o.y = fmaf(a1, inv, b1[c + 1]);
    o.z = fmaf(a2, inv, b1[c + 2]);
    o.w = fmaf(a3, inv, b1[c + 3]);
    o.x = o.x > 0.f ? o.x : 0.f;
    o.y = o.y > 0.f ? o.y : 0.f;
    o.z = o.z > 0.f ? o.z : 0.f;
    o.w = o.w > 0.f ? o.w : 0.f;
    *(float4*)&g_h1[(size_t)w * C1 + c] = o;
}

// ---------------- layer-2 aggregation + epilogue + output heads -------------
__global__ void agg2_kernel(const float* __restrict__ b2,
                            const float* __restrict__ Wm,
                            const float* __restrict__ bm,
                            const float* __restrict__ Wl,
                            const float* __restrict__ bl,
                            float* __restrict__ out) {
    int gt = blockIdx.x * blockDim.x + threadIdx.x;
    int w = gt >> 5;
    if (w >= NN) return;
    int lane = gt & 31;
    float sd = g_sdst2[w];

    // self loop
    float p = __expf(leaky(g_ssrc2[w] + sd));
    float den = p;
    float2 u = __half22float2(*(const __half2*)(g_xh2h + (size_t)w * C2 + lane * 2));
    float a0 = u.x * p, a1 = u.y * p;

    int beg = g_rowptr[w], end = g_rowptr[w + 1];
#pragma unroll 4
    for (int e = beg; e < end; ++e) {
        int s = __ldg(&g_csrc[e]);
        float pp = __expf(leaky(g_ssrc2[s] + sd));
        den += pp;
        float2 v = __half22float2(__ldg((const __half2*)(g_xh2h + (size_t)s * C2 + lane * 2)));
        a0 = fmaf(v.x, pp, a0);
        a1 = fmaf(v.y, pp, a1);
    }
    float inv = 1.f / (den + 1e-16f);
    int j0 = lane * 2;
    float v0 = fmaf(a0, inv, b2[j0]);
    float v1 = fmaf(a1, inv, b2[j0 + 1]);
    v0 = v0 > 0.f ? v0 : 0.f;
    v1 = v1 > 0.f ? v1 : 0.f;
    float m = v0 * Wm[j0] + v1 * Wm[j0 + 1];
    float l0 = v0 * Wl[j0 * 4 + 0] + v1 * Wl[(j0 + 1) * 4 + 0];
    float l1 = v0 * Wl[j0 * 4 + 1] + v1 * Wl[(j0 + 1) * 4 + 1];
    float l2 = v0 * Wl[j0 * 4 + 2] + v1 * Wl[(j0 + 1) * 4 + 2];
    float l3 = v0 * Wl[j0 * 4 + 3] + v1 * Wl[(j0 + 1) * 4 + 3];
#pragma unroll
    for (int off = 16; off > 0; off >>= 1) {
        m  += __shfl_xor_sync(0xffffffffu, m,  off);
        l0 += __shfl_xor_sync(0xffffffffu, l0, off);
        l1 += __shfl_xor_sync(0xffffffffu, l1, off);
        l2 += __shfl_xor_sync(0xffffffffu, l2, off);
        l3 += __shfl_xor_sync(0xffffffffu, l3, off);
    }
    if (lane == 0) {
        out[w] = m + bm[0];                     // mortality [N,1]
        float4 lo = make_float4(l0 + bl[0], l1 + bl[1], l2 + bl[2], l3 + bl[3]);
        *(float4*)&out[NN + (size_t)w * 4] = lo;   // los [N,4]
    }
}

// ---------------- launch ----------------------------------------------------
extern "C" void kernel_launch(void* const* d_in, const int* in_sizes, int n_in,
                              void* d_out, int out_size) {
    const float* x      = (const float*)d_in[0];
    const int*   ei     = (const int*)  d_in[1];
    const float* W1     = (const float*)d_in[2];
    const float* a_src1 = (const float*)d_in[3];
    const float* a_dst1 = (const float*)d_in[4];
    const float* b1     = (const float*)d_in[5];
    const float* W2     = (const float*)d_in[6];
    const float* a_src2 = (const float*)d_in[7];
    const float* a_dst2 = (const float*)d_in[8];
    const float* b2     = (const float*)d_in[9];
    const float* Wm     = (const float*)d_in[10];
    const float* bm     = (const float*)d_in[11];
    const float* Wl     = (const float*)d_in[12];
    const float* bl     = (const float*)d_in[13];
    float* out = (float*)d_out;

    const int gemm_blocks = (NN + 63) / 64;

    void* degAddr = nullptr;
    cudaGetSymbolAddress(&degAddr, g_deg);

    // fork a side stream for the CSR build (overlaps with gemm1).
    // created fresh each call and intentionally leaked (host objects only).
    cudaStream_t side;
    cudaStreamCreateWithFlags(&side, cudaStreamNonBlocking);
    cudaEvent_t evFork, evJoin;
    cudaEventCreateWithFlags(&evFork, cudaEventDisableTiming);
    cudaEventCreateWithFlags(&evJoin, cudaEventDisableTiming);

    cudaEventRecord(evFork, 0);
    cudaStreamWaitEvent(side, evFork, 0);

    // ---- CSR build on side stream ----
    cudaMemsetAsync(degAddr, 0, NN * sizeof(int), side);
    hist_kernel<<<(EE / 8 + 255) / 256, 256, 0, side>>>(ei);
    scan_kernel<<<1, 1024, 0, side>>>();
    scatter_kernel<<<(EE / 8 + 255) / 256, 256, 0, side>>>(ei);
    cudaEventRecord(evJoin, side);

    // ---- gemm1 on main stream (independent of CSR) ----
    gemm_kernel<1><<<gemm_blocks, 256>>>(x, W1, a_src1, a_dst1);

    // join: agg1 needs both CSR and gemm1
    cudaStreamWaitEvent(0, evJoin, 0);

    agg1_kernel<<<(NN * 32 + 255) / 256, 256>>>(b1);
    gemm_kernel<2><<<gemm_blocks, 256>>>(nullptr, W2, a_src2, a_dst2);
    agg2_kernel<<<(NN * 32 + 255) / 256, 256>>>(b2, Wm, bm, Wl, bl, out);
}

// round 7
// speedup vs baseline: 1.4474x; 1.2291x over previous
#include <cuda_runtime.h>
#include <cuda_fp16.h>
#include <math.h>

// Problem constants (fixed by the dataset)
#define NN   50000
#define EE   1600000       // edges (self loops handled analytically)
#define C1   128           // H * HID (layer 1 output channels)
#define C2   64            // layer 2 output channels

// ---------------- scratch (static device globals; no allocation) ------------
__device__ __half g_xh1h[NN * C1];  // x @ W1   (fp16 gather payload)
__device__ __half g_xh2h[NN * C2];  // h1 @ W2  (fp16 gather payload)
__device__ __half g_h1h [NN * C1];  // layer-1 output (fp16; feeds gemm2)
__device__ float  g_ssrc1[NN * 2];
__device__ float  g_sdst1[NN * 2];
__device__ float  g_ssrc2[NN];
__device__ float  g_sdst2[NN];
__device__ int    g_deg   [NN];
__device__ int    g_rowptr[NN + 1];
__device__ int    g_cursor[NN];
__device__ int    g_csrc  [EE];

__device__ __forceinline__ float leaky(float x) { return x > 0.f ? x : 0.2f * x; }

__device__ __forceinline__ unsigned smem_u32(const void* p) {
    return (unsigned)__cvta_generic_to_shared(p);
}
__device__ __forceinline__ void ldm_x4(unsigned& r0, unsigned& r1,
                                       unsigned& r2, unsigned& r3, unsigned a) {
    asm volatile("ldmatrix.sync.aligned.m8n8.x4.shared.b16 {%0,%1,%2,%3}, [%4];"
                 : "=r"(r0), "=r"(r1), "=r"(r2), "=r"(r3) : "r"(a));
}
__device__ __forceinline__ void ldm_x4_t(unsigned& r0, unsigned& r1,
                                         unsigned& r2, unsigned& r3, unsigned a) {
    asm volatile("ldmatrix.sync.aligned.m8n8.x4.trans.shared.b16 {%0,%1,%2,%3}, [%4];"
                 : "=r"(r0), "=r"(r1), "=r"(r2), "=r"(r3) : "r"(a));
}
__device__ __forceinline__ void mma16816(float* d, unsigned a0, unsigned a1,
                                         unsigned a2, unsigned a3,
                                         unsigned b0, unsigned b1) {
    asm volatile(
        "mma.sync.aligned.m16n8k16.row.col.f32.f16.f16.f32 "
        "{%0,%1,%2,%3}, {%4,%5,%6,%7}, {%8,%9}, {%0,%1,%2,%3};"
        : "+f"(d[0]), "+f"(d[1]), "+f"(d[2]), "+f"(d[3])
        : "r"(a0), "r"(a1), "r"(a2), "r"(a3), "r"(b0), "r"(b1));
}

// ---------------- CSR build (edges only; no self-loops) ---------------------
__global__ void hist_kernel(const int* __restrict__ ei) {
    int t = blockIdx.x * blockDim.x + threadIdx.x;
    if (t >= EE / 8) return;
    int4 a = ((const int4*)(ei + EE))[t * 2];
    int4 b = ((const int4*)(ei + EE))[t * 2 + 1];
    atomicAdd(&g_deg[a.x], 1);
    atomicAdd(&g_deg[a.y], 1);
    atomicAdd(&g_deg[a.z], 1);
    atomicAdd(&g_deg[a.w], 1);
    atomicAdd(&g_deg[b.x], 1);
    atomicAdd(&g_deg[b.y], 1);
    atomicAdd(&g_deg[b.z], 1);
    atomicAdd(&g_deg[b.w], 1);
}

// single-block exclusive scan, 4 elements / thread / chunk (1024 threads)
__global__ void scan_kernel() {
    __shared__ int wsum[32];
    __shared__ int carry_s;
    const int tid = threadIdx.x, lane = tid & 31, wid = tid >> 5;
    if (tid == 0) carry_s = 0;
    __syncthreads();
    for (int base = 0; base < NN; base += 4096) {
        int i0 = base + tid * 4;
        int v0 = 0, v1 = 0, v2 = 0, v3 = 0;
        if (i0 + 3 < NN) {
            int4 v = *(const int4*)&g_deg[i0];
            v0 = v.x; v1 = v.y; v2 = v.z; v3 = v.w;
        } else if (i0 < NN) {
            v0 = g_deg[i0];
            if (i0 + 1 < NN) v1 = g_deg[i0 + 1];
            if (i0 + 2 < NN) v2 = g_deg[i0 + 2];
        }
        int t = v0 + v1 + v2 + v3;
        int x = t;
#pragma unroll
        for (int off = 1; off < 32; off <<= 1) {
            int y = __shfl_up_sync(0xffffffffu, x, off);
            if (lane >= off) x += y;
        }
        if (lane == 31) wsum[wid] = x;
        __syncthreads();
        if (wid == 0) {
            int s = wsum[lane];
#pragma unroll
            for (int off = 1; off < 32; off <<= 1) {
                int y = __shfl_up_sync(0xffffffffu, s, off);
                if (lane >= off) s += y;
            }
            wsum[lane] = s;
        }
        __syncthreads();
        int carry = carry_s;
        int pref = carry + (wid ? wsum[wid - 1] : 0) + (x - t);
        if (i0 < NN)     { g_rowptr[i0]     = pref;                g_cursor[i0]     = pref; }
        if (i0 + 1 < NN) { g_rowptr[i0 + 1] = pref + v0;           g_cursor[i0 + 1] = pref + v0; }
        if (i0 + 2 < NN) { g_rowptr[i0 + 2] = pref + v0 + v1;      g_cursor[i0 + 2] = pref + v0 + v1; }
        if (i0 + 3 < NN) { g_rowptr[i0 + 3] = pref + v0 + v1 + v2; g_cursor[i0 + 3] = pref + v0 + v1 + v2; }
        __syncthreads();
        if (tid == 0) carry_s = carry + wsum[31];
        __syncthreads();
    }
    if (threadIdx.x == 0) g_rowptr[NN] = carry_s;   // == EE
}

__global__ void scatter_kernel(const int* __restrict__ ei) {
    int t = blockIdx.x * blockDim.x + threadIdx.x;
    if (t >= EE / 8) return;
    int4 sa = ((const int4*)ei)[t * 2];
    int4 sb = ((const int4*)ei)[t * 2 + 1];
    int4 da = ((const int4*)(ei + EE))[t * 2];
    int4 db = ((const int4*)(ei + EE))[t * 2 + 1];
    int p0 = atomicAdd(&g_cursor[da.x], 1);
    int p1 = atomicAdd(&g_cursor[da.y], 1);
    int p2 = atomicAdd(&g_cursor[da.z], 1);
    int p3 = atomicAdd(&g_cursor[da.w], 1);
    int p4 = atomicAdd(&g_cursor[db.x], 1);
    int p5 = atomicAdd(&g_cursor[db.y], 1);
    int p6 = atomicAdd(&g_cursor[db.z], 1);
    int p7 = atomicAdd(&g_cursor[db.w], 1);
    g_csrc[p0] = sa.x;
    g_csrc[p1] = sa.y;
    g_csrc[p2] = sa.z;
    g_csrc[p3] = sa.w;
    g_csrc[p4] = sb.x;
    g_csrc[p5] = sb.y;
    g_csrc[p6] = sb.z;
    g_csrc[p7] = sb.w;
}

// ---------------- HMMA GEMM + fused attention scores ------------------------
// LAYER 1: A = x (fp32, converted on load), tile 64x128, warps 4x2
// LAYER 2: A = g_h1h (fp16), tile 128x64, warps 8x1
// B (weights) copied row-major to smem; fragments via ldmatrix (.trans for B).
template <int LAYER>
__global__ void mma_gemm_kernel(const float* __restrict__ Afp32,
                                const float* __restrict__ W,
                                const float* __restrict__ asrc,
                                const float* __restrict__ adst) {
    constexpr int NOUT = (LAYER == 1) ? C1 : C2;
    constexpr int MT   = (LAYER == 1) ? 64 : 128;
    constexpr int LDA  = 136;            // halves per A row (pad 8)
    constexpr int LDB  = NOUT + 8;       // halves per B row (pad 8)
    __half* Hp = (LAYER == 1) ? g_xh1h : g_xh2h;
    float*  Ss = (LAYER == 1) ? g_ssrc1 : g_ssrc2;
    float*  Sd = (LAYER == 1) ? g_sdst1 : g_sdst2;

    extern __shared__ __half sm[];
    __half* As = sm;                 // [MT][LDA]
    __half* Bs = sm + MT * LDA;      // [128][LDB]

    const int tid = threadIdx.x;     // 256 threads
    const int block_row = blockIdx.x * MT;

    // ---- load A tile ----
    if constexpr (LAYER == 1) {
        for (int i = tid; i < MT * 32; i += 256) {
            int r = i >> 5, c4 = (i & 31) * 4;
            int gr = block_row + r;
            float4 v = (gr < NN) ? ((const float4*)(Afp32 + (size_t)gr * 128))[i & 31]
                                 : make_float4(0.f, 0.f, 0.f, 0.f);
            __half2 h0 = __floats2half2_rn(v.x, v.y);
            __half2 h1 = __floats2half2_rn(v.z, v.w);
            uint2 u = make_uint2(*(unsigned*)&h0, *(unsigned*)&h1);
            *(uint2*)&As[r * LDA + c4] = u;
        }
    } else {
        for (int i = tid; i < MT * 16; i += 256) {
            int r = i >> 4, c8 = (i & 15) * 8;
            int gr = block_row + r;
            uint4 u = make_uint4(0u, 0u, 0u, 0u);
            if (gr < NN) u = *(const uint4*)(g_h1h + (size_t)gr * 128 + c8);
            *(uint4*)&As[r * LDA + c8] = u;
        }
    }
    // ---- load B (row-major copy, fp32 -> fp16) ----
    for (int i = tid; i < 128 * NOUT / 8; i += 256) {
        int k = i / (NOUT / 8);
        int c8 = (i % (NOUT / 8)) * 8;
        const float4* wp = (const float4*)(W + (size_t)k * NOUT + c8);
        float4 v0 = wp[0], v1 = wp[1];
        __half2 h0 = __floats2half2_rn(v0.x, v0.y);
        __half2 h1 = __floats2half2_rn(v0.z, v0.w);
        __half2 h2 = __floats2half2_rn(v1.x, v1.y);
        __half2 h3 = __floats2half2_rn(v1.z, v1.w);
        uint4 u = make_uint4(*(unsigned*)&h0, *(unsigned*)&h1,
                             *(unsigned*)&h2, *(unsigned*)&h3);
        *(uint4*)&Bs[k * LDB + c8] = u;
    }
    __syncthreads();

    const int lane = tid & 31, wid = tid >> 5;
    const int wr = (LAYER == 1) ? (wid & 3) * 16 : wid * 16;   // warp row base
    const int wc = (LAYER == 1) ? (wid >> 2) * 64 : 0;         // warp col base

    float d[8][4];
#pragma unroll
    for (int t = 0; t < 8; ++t)
#pragma unroll
        for (int j = 0; j < 4; ++j) d[t][j] = 0.f;

    const int g = lane >> 3, lr = lane & 7;
    // A ldmatrix lane address (non-trans): row = wr+lr+(g&1)*8, col = (g>>1)*8 (+k0)
    const unsigned a_base =
        smem_u32(As) + ((unsigned)((wr + lr + (g & 1) * 8) * LDA + (g >> 1) * 8)) * 2u;
    // B ldmatrix lane address (.trans): row k = k0+(g&1)*8+lr, col = wc+(g>>1)*8 (+ntp*16)
    const unsigned b_base =
        smem_u32(Bs) + ((unsigned)(((g & 1) * 8 + lr) * LDB + wc + (g >> 1) * 8)) * 2u;

#pragma unroll
    for (int k0 = 0; k0 < 128; k0 += 16) {
        unsigned a0, a1, a2, a3;
        ldm_x4(a0, a1, a2, a3, a_base + (unsigned)(k0 * 2));
#pragma unroll
        for (int ntp = 0; ntp < 4; ++ntp) {
            unsigned b0, b1, b2, b3;
            ldm_x4_t(b0, b1, b2, b3,
                     b_base + (unsigned)((k0 * LDB + ntp * 16) * 2));
            mma16816(d[ntp * 2],     a0, a1, a2, a3, b0, b1);
            mma16816(d[ntp * 2 + 1], a0, a1, a2, a3, b2, b3);
        }
    }

    // ---- epilogue: attention scores + fp16 payload store ----
    const int cbase = wc + (lane & 3) * 2;
    float av0[8], av1[8], dv0[8], dv1[8];
#pragma unroll
    for (int t = 0; t < 8; ++t) {
        int c = cbase + t * 8;
        float2 sa = *(const float2*)&asrc[c];
        float2 sd = *(const float2*)&adst[c];
        av0[t] = sa.x; av1[t] = sa.y;
        dv0[t] = sd.x; dv1[t] = sd.y;
    }
    float ps0 = 0.f, ps8 = 0.f, pd0 = 0.f, pd8 = 0.f;
#pragma unroll
    for (int t = 0; t < 8; ++t) {
        ps0 = fmaf(d[t][0], av0[t], fmaf(d[t][1], av1[t], ps0));
        ps8 = fmaf(d[t][2], av0[t], fmaf(d[t][3], av1[t], ps8));
        pd0 = fmaf(d[t][0], dv0[t], fmaf(d[t][1], dv1[t], pd0));
        pd8 = fmaf(d[t][2], dv0[t], fmaf(d[t][3], dv1[t], pd8));
    }
#pragma unroll
    for (int off = 1; off <= 2; off <<= 1) {
        ps0 += __shfl_xor_sync(0xffffffffu, ps0, off);
        ps8 += __shfl_xor_sync(0xffffffffu, ps8, off);
        pd0 += __shfl_xor_sync(0xffffffffu, pd0, off);
        pd8 += __shfl_xor_sync(0xffffffffu, pd8, off);
    }
    const int r0 = block_row + wr + (lane >> 2);
    const int r8 = r0 + 8;
    if ((lane & 3) == 0) {
        if constexpr (LAYER == 1) {
            int h = wc >> 6;
            if (r0 < NN) { Ss[r0 * 2 + h] = ps0; Sd[r0 * 2 + h] = pd0; }
            if (r8 < NN) { Ss[r8 * 2 + h] = ps8; Sd[r8 * 2 + h] = pd8; }
        } else {
            if (r0 < NN) { Ss[r0] = ps0; Sd[r0] = pd0; }
            if (r8 < NN) { Ss[r8] = ps8; Sd[r8] = pd8; }
        }
    }
#pragma unroll
    for (int t = 0; t < 8; ++t) {
        int c = cbase + t * 8;
        if (r0 < NN)
            *(__half2*)&Hp[(size_t)r0 * NOUT + c] = __floats2half2_rn(d[t][0], d[t][1]);
        if (r8 < NN)
            *(__half2*)&Hp[(size_t)r8 * NOUT + c] = __floats2half2_rn(d[t][2], d[t][3]);
    }
}

// ---------------- layer-1 aggregation: warp per dst node, fp16 gather -------
// softmax without max-subtraction (shift-invariant); self-loop added analytically
__global__ void agg1_kernel(const float* __restrict__ b1) {
    int gt = blockIdx.x * blockDim.x + threadIdx.x;
    int w = gt >> 5;
    if (w >= NN) return;
    int lane = gt & 31;
    int h = lane >> 4;
    float sd = g_sdst1[w * 2 + h];

    // self loop (src == dst == w)
    float p = __expf(leaky(g_ssrc1[w * 2 + h] + sd));
    float den = p;
    uint2 raw = *(const uint2*)(g_xh1h + (size_t)w * C1 + lane * 4);
    float2 u0 = __half22float2(*(__half2*)&raw.x);
    float2 u1 = __half22float2(*(__half2*)&raw.y);
    float a0 = u0.x * p, a1 = u0.y * p, a2 = u1.x * p, a3 = u1.y * p;

    int beg = g_rowptr[w], end = g_rowptr[w + 1];
#pragma unroll 4
    for (int e = beg; e < end; ++e) {
        int s = __ldg(&g_csrc[e]);
        float pp = __expf(leaky(g_ssrc1[s * 2 + h] + sd));
        den += pp;
        uint2 rw = __ldg((const uint2*)(g_xh1h + (size_t)s * C1 + lane * 4));
        float2 v0 = __half22float2(*(__half2*)&rw.x);
        float2 v1 = __half22float2(*(__half2*)&rw.y);
        a0 = fmaf(v0.x, pp, a0);
        a1 = fmaf(v0.y, pp, a1);
        a2 = fmaf(v1.x, pp, a2);
        a3 = fmaf(v1.y, pp, a3);
    }
    float inv = 1.f / (den + 1e-16f);
    int c = lane * 4;
    float o0 = fmaf(a0, inv, b1[c]);
    float o1 = fmaf(a1, inv, b1[c + 1]);
    float o2 = fmaf(a2, inv, b1[c + 2]);
    float o3 = fmaf(a3, inv, b1[c + 3]);
    o0 = o0 > 0.f ? o0 : 0.f;
    o1 = o1 > 0.f ? o1 : 0.f;
    o2 = o2 > 0.f ? o2 : 0.f;
    o3 = o3 > 0.f ? o3 : 0.f;
    __half2 h0 = __floats2half2_rn(o0, o1);
    __half2 h1 = __floats2half2_rn(o2, o3);
    *(uint2*)&g_h1h[(size_t)w * C1 + c] = make_uint2(*(unsigned*)&h0, *(unsigned*)&h1);
}

// ---------------- layer-2 aggregation + epilogue + output heads -------------
__global__ void agg2_kernel(const float* __restrict__ b2,
                            const float* __restrict__ Wm,
                            const float* __restrict__ bm,
                            const float* __restrict__ Wl,
                            const float* __restrict__ bl,
                            float* __restrict__ out) {
    int gt = blockIdx.x * blockDim.x + threadIdx.x;
    int w = gt >> 5;
    if (w >= NN) return;
    int lane = gt & 31;
    float sd = g_sdst2[w];

    // self loop
    float p = __expf(leaky(g_ssrc2[w] + sd));
    float den = p;
    float2 u = __half22float2(*(const __half2*)(g_xh2h + (size_t)w * C2 + lane * 2));
    float a0 = u.x * p, a1 = u.y * p;

    int beg = g_rowptr[w], end = g_rowptr[w + 1];
#pragma unroll 4
    for (int e = beg; e < end; ++e) {
        int s = __ldg(&g_csrc[e]);
        float pp = __expf(leaky(g_ssrc2[s] + sd));
        den += pp;
        float2 v = __half22float2(__ldg((const __half2*)(g_xh2h + (size_t)s * C2 + lane * 2)));
        a0 = fmaf(v.x, pp, a0);
        a1 = fmaf(v.y, pp, a1);
    }
    float inv = 1.f / (den + 1e-16f);
    int j0 = lane * 2;
    float v0 = fmaf(a0, inv, b2[j0]);
    float v1 = fmaf(a1, inv, b2[j0 + 1]);
    v0 = v0 > 0.f ? v0 : 0.f;
    v1 = v1 > 0.f ? v1 : 0.f;
    float m = v0 * Wm[j0] + v1 * Wm[j0 + 1];
    float l0 = v0 * Wl[j0 * 4 + 0] + v1 * Wl[(j0 + 1) * 4 + 0];
    float l1 = v0 * Wl[j0 * 4 + 1] + v1 * Wl[(j0 + 1) * 4 + 1];
    float l2 = v0 * Wl[j0 * 4 + 2] + v1 * Wl[(j0 + 1) * 4 + 2];
    float l3 = v0 * Wl[j0 * 4 + 3] + v1 * Wl[(j0 + 1) * 4 + 3];
#pragma unroll
    for (int off = 16; off > 0; off >>= 1) {
        m  += __shfl_xor_sync(0xffffffffu, m,  off);
        l0 += __shfl_xor_sync(0xffffffffu, l0, off);
        l1 += __shfl_xor_sync(0xffffffffu, l1, off);
        l2 += __shfl_xor_sync(0xffffffffu, l2, off);
        l3 += __shfl_xor_sync(0xffffffffu, l3, off);
    }
    if (lane == 0) {
        out[w] = m + bm[0];                     // mortality [N,1]
        float4 lo = make_float4(l0 + bl[0], l1 + bl[1], l2 + bl[2], l3 + bl[3]);
        *(float4*)&out[NN + (size_t)w * 4] = lo;   // los [N,4]
    }
}

// ---------------- launch ----------------------------------------------------
extern "C" void kernel_launch(void* const* d_in, const int* in_sizes, int n_in,
                              void* d_out, int out_size) {
    const float* x      = (const float*)d_in[0];
    const int*   ei     = (const int*)  d_in[1];
    const float* W1     = (const float*)d_in[2];
    const float* a_src1 = (const float*)d_in[3];
    const float* a_dst1 = (const float*)d_in[4];
    const float* b1     = (const float*)d_in[5];
    const float* W2     = (const float*)d_in[6];
    const float* a_src2 = (const float*)d_in[7];
    const float* a_dst2 = (const float*)d_in[8];
    const float* b2     = (const float*)d_in[9];
    const float* Wm     = (const float*)d_in[10];
    const float* bm     = (const float*)d_in[11];
    const float* Wl     = (const float*)d_in[12];
    const float* bl     = (const float*)d_in[13];
    float* out = (float*)d_out;

    // dynamic smem: L1 = (64*136 + 128*136)*2 = 52224 ; L2 = (128*136 + 128*72)*2 = 53248
    const int smem1 = (64 * 136 + 128 * 136) * 2;
    const int smem2 = (128 * 136 + 128 * 72) * 2;
    cudaFuncSetAttribute(mma_gemm_kernel<1>,
                         cudaFuncAttributeMaxDynamicSharedMemorySize, smem1);
    cudaFuncSetAttribute(mma_gemm_kernel<2>,
                         cudaFuncAttributeMaxDynamicSharedMemorySize, smem2);

    void* degAddr = nullptr;
    cudaGetSymbolAddress(&degAddr, g_deg);

    // fork a side stream for the CSR build (overlaps with gemm1).
    // created fresh each call and intentionally leaked (host objects only).
    cudaStream_t side;
    cudaStreamCreateWithFlags(&side, cudaStreamNonBlocking);
    cudaEvent_t evFork, evJoin;
    cudaEventCreateWithFlags(&evFork, cudaEventDisableTiming);
    cudaEventCreateWithFlags(&evJoin, cudaEventDisableTiming);

    cudaEventRecord(evFork, 0);
    cudaStreamWaitEvent(side, evFork, 0);

    // ---- CSR build on side stream ----
    cudaMemsetAsync(degAddr, 0, NN * sizeof(int), side);
    hist_kernel<<<(EE / 8 + 255) / 256, 256, 0, side>>>(ei);
    scan_kernel<<<1, 1024, 0, side>>>();
    scatter_kernel<<<(EE / 8 + 255) / 256, 256, 0, side>>>(ei);
    cudaEventRecord(evJoin, side);

    // ---- gemm1 on main stream (independent of CSR) ----
    mma_gemm_kernel<1><<<(NN + 63) / 64, 256, smem1>>>(x, W1, a_src1, a_dst1);

    // join: agg1 needs both CSR and gemm1
    cudaStreamWaitEvent(0, evJoin, 0);

    agg1_kernel<<<(NN * 32 + 255) / 256, 256>>>(b1);
    mma_gemm_kernel<2><<<(NN + 127) / 128, 256, smem2>>>(nullptr, W2, a_src2, a_dst2);
    agg2_kernel<<<(NN * 32 + 255) / 256, 256>>>(b2, Wm, bm, Wl, bl, out);
}